// round 4
// baseline (speedup 1.0000x reference)
#include <cuda_runtime.h>

// out = 1 - log10(sqrt(N*(x-y)^2) + 1),  N = 1024^2  =>  1 - log10(1024*|x-y| + 1)
// HBM-bound streaming: 2 fp32 in + 1 fp32 out, 33.5M elems (402.7 MB).
// R4: 2 float4s per thread (split-stride i and i+half) -> MLP_p1=4 with plain
//     intrinsic loads, keeping regs ~26 and occupancy high. 128-thread blocks.

__device__ __forceinline__ float jfn(float a, float b) {
    return 1.0f - __log10f(fmaf(1024.0f, fabsf(a - b), 1.0f));
}

__device__ __forceinline__ float4 jfn4(float4 a, float4 b) {
    float4 r;
    r.x = jfn(a.x, b.x);
    r.y = jfn(a.y, b.y);
    r.z = jfn(a.z, b.z);
    r.w = jfn(a.w, b.w);
    return r;
}

// Each thread handles float4 indices i and i+half (half = n4/2).
__global__ void __launch_bounds__(128) jsim_kernel_x2(
    const float4* __restrict__ x,
    const float4* __restrict__ y,
    float4* __restrict__ out,
    int half)
{
    int i = blockIdx.x * blockDim.x + threadIdx.x;
    if (i >= half) return;
    int j = i + half;

    // Front-batch all four loads (independent -> MLP 4).
    float4 a0 = __ldcs(x + i);
    float4 a1 = __ldcs(x + j);
    float4 b0 = __ldcs(y + i);
    float4 b1 = __ldcs(y + j);

    __stcs(out + i, jfn4(a0, b0));
    __stcs(out + j, jfn4(a1, b1));
}

// Fallback single-float4 kernel (covers odd middle element if n4 is odd).
__global__ void __launch_bounds__(128) jsim_kernel_v4(
    const float4* __restrict__ x,
    const float4* __restrict__ y,
    float4* __restrict__ out,
    int start, int n4)
{
    int i = start + blockIdx.x * blockDim.x + threadIdx.x;
    if (i >= n4) return;
    __stcs(out + i, jfn4(__ldcs(x + i), __ldcs(y + i)));
}

// Scalar tail for n % 4 != 0 (not hit for this shape; kept for generality).
__global__ void jsim_kernel_tail(
    const float* __restrict__ x,
    const float* __restrict__ y,
    float* __restrict__ out,
    int start, int n)
{
    int i = start + blockIdx.x * blockDim.x + threadIdx.x;
    if (i >= n) return;
    out[i] = jfn(x[i], y[i]);
}

extern "C" void kernel_launch(void* const* d_in, const int* in_sizes, int n_in,
                              void* d_out, int out_size)
{
    const float* x = (const float*)d_in[0];
    const float* y = (const float*)d_in[1];
    float* out = (float*)d_out;

    int n = in_sizes[0];
    int n4 = n / 4;
    int half = n4 / 2;

    if (half > 0) {
        const int threads = 128;
        int blocks = (half + threads - 1) / threads;
        jsim_kernel_x2<<<blocks, threads>>>(
            (const float4*)x, (const float4*)y, (float4*)out, half);
    }
    // Odd float4 (only if n4 is odd): index 2*half .. n4-1 (at most 1 element).
    if (n4 > 2 * half) {
        jsim_kernel_v4<<<1, 128>>>(
            (const float4*)x, (const float4*)y, (float4*)out, 2 * half, n4);
    }

    int rem_start = n4 * 4;
    if (n - rem_start > 0) {
        jsim_kernel_tail<<<1, 128>>>(x, y, out, rem_start, n);
    }
}

// round 5
// speedup vs baseline: 1.0041x; 1.0041x over previous
#include <cuda_runtime.h>

// out = 1 - log10(sqrt(N*(x-y)^2) + 1),  N = 1024^2  =>  1 - log10(1024*|x-y| + 1)
// HBM-bound streaming: 2 fp32 in + 1 fp32 out, 33.5M elems (402.7 MB).
// R5: 256-bit vector accesses (sm_100+ ld/st.global.v8.f32 -> LDG.E.256),
//     one v8 per thread, flat grid, 256-thread blocks.

__device__ __forceinline__ float jfn(float a, float b) {
    return 1.0f - __log10f(fmaf(1024.0f, fabsf(a - b), 1.0f));
}

struct v8 { float f[8]; };

__device__ __forceinline__ v8 ldg256(const float* p) {
    v8 v;
    asm volatile("ld.global.nc.v8.f32 {%0,%1,%2,%3,%4,%5,%6,%7}, [%8];"
                 : "=f"(v.f[0]), "=f"(v.f[1]), "=f"(v.f[2]), "=f"(v.f[3]),
                   "=f"(v.f[4]), "=f"(v.f[5]), "=f"(v.f[6]), "=f"(v.f[7])
                 : "l"(p));
    return v;
}

__device__ __forceinline__ void stg256(float* p, const v8& v) {
    asm volatile("st.global.v8.f32 [%0], {%1,%2,%3,%4,%5,%6,%7,%8};"
                 :: "l"(p),
                    "f"(v.f[0]), "f"(v.f[1]), "f"(v.f[2]), "f"(v.f[3]),
                    "f"(v.f[4]), "f"(v.f[5]), "f"(v.f[6]), "f"(v.f[7])
                 : "memory");
}

__global__ void __launch_bounds__(256) jsim_kernel_v8(
    const float* __restrict__ x,
    const float* __restrict__ y,
    float* __restrict__ out,
    int n8)
{
    int i = blockIdx.x * blockDim.x + threadIdx.x;
    if (i >= n8) return;
    long long off = (long long)i * 8;

    v8 a = ldg256(x + off);
    v8 b = ldg256(y + off);

    v8 r;
    #pragma unroll
    for (int k = 0; k < 8; k++) r.f[k] = jfn(a.f[k], b.f[k]);

    stg256(out + off, r);
}

// float4 fallback for the chunk between n8*8 and n4*4.
__global__ void __launch_bounds__(128) jsim_kernel_v4(
    const float4* __restrict__ x,
    const float4* __restrict__ y,
    float4* __restrict__ out,
    int start, int n4)
{
    int i = start + blockIdx.x * blockDim.x + threadIdx.x;
    if (i >= n4) return;
    float4 a = __ldcs(x + i);
    float4 b = __ldcs(y + i);
    float4 r;
    r.x = jfn(a.x, b.x);
    r.y = jfn(a.y, b.y);
    r.z = jfn(a.z, b.z);
    r.w = jfn(a.w, b.w);
    __stcs(out + i, r);
}

// Scalar tail for n % 4 != 0 (not hit for this shape; kept for generality).
__global__ void jsim_kernel_tail(
    const float* __restrict__ x,
    const float* __restrict__ y,
    float* __restrict__ out,
    int start, int n)
{
    int i = start + blockIdx.x * blockDim.x + threadIdx.x;
    if (i >= n) return;
    out[i] = jfn(x[i], y[i]);
}

extern "C" void kernel_launch(void* const* d_in, const int* in_sizes, int n_in,
                              void* d_out, int out_size)
{
    const float* x = (const float*)d_in[0];
    const float* y = (const float*)d_in[1];
    float* out = (float*)d_out;

    int n = in_sizes[0];
    int n8 = n / 8;
    int n4 = n / 4;

    if (n8 > 0) {
        const int threads = 256;
        int blocks = (n8 + threads - 1) / threads;
        jsim_kernel_v8<<<blocks, threads>>>(x, y, out, n8);
    }
    // Middle float4 (only if n4 is odd): covers [n8*2, n4).
    if (n4 > n8 * 2) {
        jsim_kernel_v4<<<1, 128>>>(
            (const float4*)x, (const float4*)y, (float4*)out, n8 * 2, n4);
    }
    int rem_start = n4 * 4;
    if (n - rem_start > 0) {
        jsim_kernel_tail<<<1, 128>>>(x, y, out, rem_start, n);
    }
}

// round 6
// speedup vs baseline: 1.0047x; 1.0005x over previous
#include <cuda_runtime.h>

// out = 1 - log10(sqrt(N*(x-y)^2) + 1),  N = 1024^2  =>  1 - log10(1024*|x-y| + 1)
// HBM-bound streaming: 2 fp32 in + 1 fp32 out, 33.5M elems (402.7 MB).
// R6: 256-bit vector accesses (LDG.E.256/STG.E.256) + .cs evict-first policy
//     on both loads and stores (touch-once data). One v8/thread, flat grid.

__device__ __forceinline__ float jfn(float a, float b) {
    return 1.0f - __log10f(fmaf(1024.0f, fabsf(a - b), 1.0f));
}

struct v8 { float f[8]; };

__device__ __forceinline__ v8 ldgcs256(const float* p) {
    v8 v;
    asm volatile("ld.global.cs.v8.f32 {%0,%1,%2,%3,%4,%5,%6,%7}, [%8];"
                 : "=f"(v.f[0]), "=f"(v.f[1]), "=f"(v.f[2]), "=f"(v.f[3]),
                   "=f"(v.f[4]), "=f"(v.f[5]), "=f"(v.f[6]), "=f"(v.f[7])
                 : "l"(p));
    return v;
}

__device__ __forceinline__ void stgcs256(float* p, const v8& v) {
    asm volatile("st.global.cs.v8.f32 [%0], {%1,%2,%3,%4,%5,%6,%7,%8};"
                 :: "l"(p),
                    "f"(v.f[0]), "f"(v.f[1]), "f"(v.f[2]), "f"(v.f[3]),
                    "f"(v.f[4]), "f"(v.f[5]), "f"(v.f[6]), "f"(v.f[7])
                 : "memory");
}

__global__ void __launch_bounds__(256) jsim_kernel_v8cs(
    const float* __restrict__ x,
    const float* __restrict__ y,
    float* __restrict__ out,
    int n8)
{
    int i = blockIdx.x * blockDim.x + threadIdx.x;
    if (i >= n8) return;
    long long off = (long long)i * 8;

    v8 a = ldgcs256(x + off);
    v8 b = ldgcs256(y + off);

    v8 r;
    #pragma unroll
    for (int k = 0; k < 8; k++) r.f[k] = jfn(a.f[k], b.f[k]);

    stgcs256(out + off, r);
}

// float4 fallback for the chunk between n8*8 and n4*4 (not hit for this shape).
__global__ void __launch_bounds__(128) jsim_kernel_v4(
    const float4* __restrict__ x,
    const float4* __restrict__ y,
    float4* __restrict__ out,
    int start, int n4)
{
    int i = start + blockIdx.x * blockDim.x + threadIdx.x;
    if (i >= n4) return;
    float4 a = __ldcs(x + i);
    float4 b = __ldcs(y + i);
    float4 r;
    r.x = jfn(a.x, b.x);
    r.y = jfn(a.y, b.y);
    r.z = jfn(a.z, b.z);
    r.w = jfn(a.w, b.w);
    __stcs(out + i, r);
}

// Scalar tail for n % 4 != 0 (not hit for this shape; kept for generality).
__global__ void jsim_kernel_tail(
    const float* __restrict__ x,
    const float* __restrict__ y,
    float* __restrict__ out,
    int start, int n)
{
    int i = start + blockIdx.x * blockDim.x + threadIdx.x;
    if (i >= n) return;
    out[i] = jfn(x[i], y[i]);
}

extern "C" void kernel_launch(void* const* d_in, const int* in_sizes, int n_in,
                              void* d_out, int out_size)
{
    const float* x = (const float*)d_in[0];
    const float* y = (const float*)d_in[1];
    float* out = (float*)d_out;

    int n = in_sizes[0];
    int n8 = n / 8;
    int n4 = n / 4;

    if (n8 > 0) {
        const int threads = 256;
        int blocks = (n8 + threads - 1) / threads;
        jsim_kernel_v8cs<<<blocks, threads>>>(x, y, out, n8);
    }
    if (n4 > n8 * 2) {
        jsim_kernel_v4<<<1, 128>>>(
            (const float4*)x, (const float4*)y, (float4*)out, n8 * 2, n4);
    }
    int rem_start = n4 * 4;
    if (n - rem_start > 0) {
        jsim_kernel_tail<<<1, 128>>>(x, y, out, rem_start, n);
    }
}